// round 1
// baseline (speedup 1.0000x reference)
#include <cuda_runtime.h>

// Attention_2362232013200 — B=256, S=196, D=2048, H=512, all fp32.
// Pipeline: K1 gemm(split-K) -> K1 reduce(+bias) -> K2 scores(tanh dot)
//           -> K3 softmax+mask renorm -> K4 weighted sum over att_feats.

constexpr int B = 256;
constexpr int S = 196;
constexpr int D = 2048;
constexpr int H = 512;
constexpr int KS = 16;          // split-K factor for K1
constexpr int KC = D / KS;      // 128 K per split

// ---- scratch (device globals; no allocations allowed) ----
__device__ __align__(16) float g_part[KS * B * H];   // 8 MB split-K partials
__device__ __align__(16) float g_att_h[B * H];       // [B,H]
__device__ __align__(16) float g_scores[B * S];      // [B,S]
__device__ __align__(16) float g_weight[B * S];      // [B,S]

__device__ __forceinline__ float tanh_fast(float x) {
    // tanh(x) = 1 - 2/(exp(2x)+1); saturates correctly for |x| large.
    float e = __expf(2.0f * x);
    return 1.0f - __fdividef(2.0f, e + 1.0f);
}

// ---------------------------------------------------------------------------
// K1a: split-K SGEMM partials. att_h_part[ks][b][h] = sum_{k in chunk} h[b,k]*W[h,k]
// Tiles: BM=64, BN=64, BK=16. 256 threads, 4x4 microtile each.
// Grid: (256/64, 512/64, KS) = (4, 8, 16) = 512 blocks.
// ---------------------------------------------------------------------------
__global__ __launch_bounds__(256) void k1_gemm(const float* __restrict__ A,
                                               const float* __restrict__ Wm) {
    __shared__ __align__(16) float As[16][68];   // [k][m], padded
    __shared__ __align__(16) float Bs[16][68];   // [k][n], padded

    const int bm = blockIdx.x * 64;
    const int bn = blockIdx.y * 64;
    const int k0 = blockIdx.z * KC;

    const int tid = threadIdx.x;
    const int tx = tid & 15;        // 0..15 -> n
    const int ty = tid >> 4;        // 0..15 -> m
    const int lr = tid >> 2;        // loader row 0..63
    const int lk = (tid & 3) << 2;  // loader k offset 0,4,8,12

    const float* Ap = A  + (size_t)(bm + lr) * D + k0 + lk;
    const float* Bp = Wm + (size_t)(bn + lr) * D + k0 + lk;

    float acc[4][4] = {};

    for (int kt = 0; kt < KC / 16; ++kt) {
        float4 av = *(const float4*)(Ap + kt * 16);
        float4 bv = *(const float4*)(Bp + kt * 16);
        if (kt) __syncthreads();
        As[lk + 0][lr] = av.x; As[lk + 1][lr] = av.y;
        As[lk + 2][lr] = av.z; As[lk + 3][lr] = av.w;
        Bs[lk + 0][lr] = bv.x; Bs[lk + 1][lr] = bv.y;
        Bs[lk + 2][lr] = bv.z; Bs[lk + 3][lr] = bv.w;
        __syncthreads();
#pragma unroll
        for (int kk = 0; kk < 16; ++kk) {
            float4 a4 = *(const float4*)&As[kk][ty * 4];
            float4 b4 = *(const float4*)&Bs[kk][tx * 4];
            acc[0][0] += a4.x * b4.x; acc[0][1] += a4.x * b4.y;
            acc[0][2] += a4.x * b4.z; acc[0][3] += a4.x * b4.w;
            acc[1][0] += a4.y * b4.x; acc[1][1] += a4.y * b4.y;
            acc[1][2] += a4.y * b4.z; acc[1][3] += a4.y * b4.w;
            acc[2][0] += a4.z * b4.x; acc[2][1] += a4.z * b4.y;
            acc[2][2] += a4.z * b4.z; acc[2][3] += a4.z * b4.w;
            acc[3][0] += a4.w * b4.x; acc[3][1] += a4.w * b4.y;
            acc[3][2] += a4.w * b4.z; acc[3][3] += a4.w * b4.w;
        }
    }

    float* po = g_part + (size_t)blockIdx.z * (B * H) +
                (size_t)(bm + ty * 4) * H + bn + tx * 4;
#pragma unroll
    for (int r = 0; r < 4; ++r) {
        *(float4*)(po + (size_t)r * H) =
            make_float4(acc[r][0], acc[r][1], acc[r][2], acc[r][3]);
    }
}

// K1b: reduce split-K partials + bias -> g_att_h. Grid 512 x 256.
__global__ __launch_bounds__(256) void k1_reduce(const float* __restrict__ bias) {
    const int idx = blockIdx.x * 256 + threadIdx.x;   // < B*H
    float s = bias[idx & (H - 1)];
#pragma unroll
    for (int k = 0; k < KS; ++k) s += g_part[(size_t)k * (B * H) + idx];
    g_att_h[idx] = s;
}

// ---------------------------------------------------------------------------
// K2: scores[b,s] = sum_h w_alpha[h]*tanh(p[b,s,h] + att_h[b,h]) + b_alpha
// Grid (B, 7); 256 threads; each warp handles s rows w, w+8, w+16, w+24.
// ---------------------------------------------------------------------------
__global__ __launch_bounds__(256) void k2_scores(const float* __restrict__ p_att,
                                                 const float* __restrict__ w_alpha,
                                                 const float* __restrict__ b_alpha) {
    __shared__ __align__(16) float ah[H];
    __shared__ __align__(16) float wa[H];

    const int b = blockIdx.x;
    const int s0 = blockIdx.y * 28;
    const int tid = threadIdx.x;

    ah[tid]       = g_att_h[b * H + tid];
    ah[tid + 256] = g_att_h[b * H + tid + 256];
    wa[tid]       = w_alpha[tid];
    wa[tid + 256] = w_alpha[tid + 256];
    __syncthreads();

    const int w = tid >> 5, l = tid & 31;
    const float ba = b_alpha[0];

    for (int r = w; r < 28; r += 8) {
        const int s = s0 + r;
        const float4* pp = (const float4*)(p_att + (size_t)(b * S + s) * H);
        float acc = 0.f;
#pragma unroll
        for (int j = 0; j < 4; ++j) {
            const int hi = j * 32 + l;               // float4 index into H/4
            float4 p4 = pp[hi];
            float4 a4 = *(const float4*)&ah[hi * 4];
            float4 w4 = *(const float4*)&wa[hi * 4];
            acc += w4.x * tanh_fast(p4.x + a4.x);
            acc += w4.y * tanh_fast(p4.y + a4.y);
            acc += w4.z * tanh_fast(p4.z + a4.z);
            acc += w4.w * tanh_fast(p4.w + a4.w);
        }
#pragma unroll
        for (int o = 16; o; o >>= 1) acc += __shfl_xor_sync(0xFFFFFFFFu, acc, o);
        if (l == 0) g_scores[b * S + s] = acc + ba;
    }
}

// ---------------------------------------------------------------------------
// K3: softmax over S, then mask-multiply and renormalize. Grid B x 256.
// ---------------------------------------------------------------------------
__global__ __launch_bounds__(256) void k3_softmax(const float* __restrict__ mask) {
    __shared__ float red[256];
    const int b = blockIdx.x, tid = threadIdx.x;

    float sc = (tid < S) ? g_scores[b * S + tid] : -1e30f;

    red[tid] = sc; __syncthreads();
    for (int o = 128; o; o >>= 1) {
        if (tid < o) red[tid] = fmaxf(red[tid], red[tid + o]);
        __syncthreads();
    }
    const float mx = red[0]; __syncthreads();

    float e = (tid < S) ? __expf(sc - mx) : 0.f;
    red[tid] = e; __syncthreads();
    for (int o = 128; o; o >>= 1) {
        if (tid < o) red[tid] += red[tid + o];
        __syncthreads();
    }
    const float inv = 1.f / red[0]; __syncthreads();

    float wgt = (tid < S) ? e * inv * mask[b * S + tid] : 0.f;
    red[tid] = wgt; __syncthreads();
    for (int o = 128; o; o >>= 1) {
        if (tid < o) red[tid] += red[tid + o];
        __syncthreads();
    }
    const float inv2 = 1.f / red[0];
    if (tid < S) g_weight[b * S + tid] = wgt * inv2;
}

// ---------------------------------------------------------------------------
// K4: att_res[b,d] = sum_s weight[b,s] * att_feats[b,s,d]
// Grid (B, 4); 128 threads; each thread owns 4 consecutive d (float4).
// ---------------------------------------------------------------------------
__global__ __launch_bounds__(128) void k4_wsum(const float* __restrict__ feats,
                                               float* __restrict__ out) {
    __shared__ float ws[S];
    const int b = blockIdx.x;
    const int dbase = blockIdx.y * 512 + threadIdx.x * 4;

    for (int i = threadIdx.x; i < S; i += 128) ws[i] = g_weight[b * S + i];
    __syncthreads();

    const float4* fp = (const float4*)(feats + (size_t)b * S * D + dbase);
    float4 acc = make_float4(0.f, 0.f, 0.f, 0.f);
#pragma unroll 4
    for (int s = 0; s < S; ++s) {
        float4 f = fp[(size_t)s * (D / 4)];
        const float w = ws[s];
        acc.x += w * f.x; acc.y += w * f.y;
        acc.z += w * f.z; acc.w += w * f.w;
    }
    *(float4*)(out + (size_t)b * D + dbase) = acc;
}

// ---------------------------------------------------------------------------
extern "C" void kernel_launch(void* const* d_in, const int* in_sizes, int n_in,
                              void* d_out, int out_size) {
    const float* h         = (const float*)d_in[0];   // [B,D]
    const float* att_feats = (const float*)d_in[1];   // [B,S,D]
    const float* p_att     = (const float*)d_in[2];   // [B,S,H]
    const float* mask      = (const float*)d_in[3];   // [B,S]
    const float* W         = (const float*)d_in[4];   // [H,D]
    const float* b_h2att   = (const float*)d_in[5];   // [H]
    const float* w_alpha   = (const float*)d_in[6];   // [H]
    const float* b_alpha   = (const float*)d_in[7];   // scalar
    float* out = (float*)d_out;                        // [B,D]

    k1_gemm   <<<dim3(B / 64, H / 64, KS), 256>>>(h, W);
    k1_reduce <<<dim3((B * H) / 256), 256>>>(b_h2att);
    k2_scores <<<dim3(B, 7), 256>>>(p_att, w_alpha, b_alpha);
    k3_softmax<<<dim3(B), 256>>>(mask);
    k4_wsum   <<<dim3(B, 4), 128>>>(att_feats, out);
}

// round 2
// speedup vs baseline: 1.1920x; 1.1920x over previous
#include <cuda_runtime.h>

// Attention_2362232013200 — B=256, S=196, D=2048, H=512, all fp32.
// R2: k1 uses fma.rn.f32x2 packed FMA; k2+k3 fused (scores+softmax+renorm);
//     tanh via MUFU tanh.approx.f32; b_alpha dropped (cancels in softmax).

constexpr int B = 256;
constexpr int S = 196;
constexpr int D = 2048;
constexpr int H = 512;
constexpr int KS = 16;          // split-K factor for K1
constexpr int KC = D / KS;      // 128 K per split

// ---- scratch (device globals; no allocations allowed) ----
__device__ __align__(16) float g_part[KS * B * H];   // 8 MB split-K partials
__device__ __align__(16) float g_att_h[B * H];       // [B,H]
__device__ __align__(16) float g_weight[B * S];      // [B,S]

__device__ __forceinline__ float tanh_approx(float x) {
    float r;
    asm("tanh.approx.f32 %0, %1;" : "=f"(r) : "f"(x));
    return r;
}

__device__ __forceinline__ unsigned long long pack2(float lo, float hi) {
    unsigned long long r;
    asm("mov.b64 %0, {%1, %2};" : "=l"(r) : "f"(lo), "f"(hi));
    return r;
}
__device__ __forceinline__ void unpack2(unsigned long long v, float& lo, float& hi) {
    asm("mov.b64 {%0, %1}, %2;" : "=f"(lo), "=f"(hi) : "l"(v));
}
__device__ __forceinline__ void ffma2(unsigned long long& acc,
                                      unsigned long long a,
                                      unsigned long long b) {
    asm("fma.rn.f32x2 %0, %1, %2, %0;" : "+l"(acc) : "l"(a), "l"(b));
}

// ---------------------------------------------------------------------------
// K1a: split-K SGEMM partials via packed f32x2 FMA.
// Tiles: BM=64, BN=64, BK=16. 256 threads, 4x4 microtile each.
// Grid: (4, 8, 16) = 512 blocks.
// ---------------------------------------------------------------------------
__global__ __launch_bounds__(256) void k1_gemm(const float* __restrict__ A,
                                               const float* __restrict__ Wm) {
    __shared__ __align__(16) float As[16][68];   // [k][m], padded
    __shared__ __align__(16) float Bs[16][68];   // [k][n], padded

    const int bm = blockIdx.x * 64;
    const int bn = blockIdx.y * 64;
    const int k0 = blockIdx.z * KC;

    const int tid = threadIdx.x;
    const int tx = tid & 15;        // 0..15 -> n
    const int ty = tid >> 4;        // 0..15 -> m
    const int lr = tid >> 2;        // loader row 0..63
    const int lk = (tid & 3) << 2;  // loader k offset 0,4,8,12

    const float* Ap = A  + (size_t)(bm + lr) * D + k0 + lk;
    const float* Bp = Wm + (size_t)(bn + lr) * D + k0 + lk;

    // acc[r][p]: row r (m), pair p covers n-cols {2p, 2p+1}
    unsigned long long acc[4][2] = {};

    for (int kt = 0; kt < KC / 16; ++kt) {
        float4 av = *(const float4*)(Ap + kt * 16);
        float4 bv = *(const float4*)(Bp + kt * 16);
        if (kt) __syncthreads();
        As[lk + 0][lr] = av.x; As[lk + 1][lr] = av.y;
        As[lk + 2][lr] = av.z; As[lk + 3][lr] = av.w;
        Bs[lk + 0][lr] = bv.x; Bs[lk + 1][lr] = bv.y;
        Bs[lk + 2][lr] = bv.z; Bs[lk + 3][lr] = bv.w;
        __syncthreads();
#pragma unroll
        for (int kk = 0; kk < 16; ++kk) {
            float4 a4 = *(const float4*)&As[kk][ty * 4];
            float4 b4 = *(const float4*)&Bs[kk][tx * 4];
            unsigned long long b01 = pack2(b4.x, b4.y);
            unsigned long long b23 = pack2(b4.z, b4.w);
            unsigned long long a0 = pack2(a4.x, a4.x);
            unsigned long long a1 = pack2(a4.y, a4.y);
            unsigned long long a2 = pack2(a4.z, a4.z);
            unsigned long long a3 = pack2(a4.w, a4.w);
            ffma2(acc[0][0], a0, b01); ffma2(acc[0][1], a0, b23);
            ffma2(acc[1][0], a1, b01); ffma2(acc[1][1], a1, b23);
            ffma2(acc[2][0], a2, b01); ffma2(acc[2][1], a2, b23);
            ffma2(acc[3][0], a3, b01); ffma2(acc[3][1], a3, b23);
        }
    }

    float* po = g_part + (size_t)blockIdx.z * (B * H) +
                (size_t)(bm + ty * 4) * H + bn + tx * 4;
#pragma unroll
    for (int r = 0; r < 4; ++r) {
        float4 o;
        unpack2(acc[r][0], o.x, o.y);
        unpack2(acc[r][1], o.z, o.w);
        *(float4*)(po + (size_t)r * H) = o;
    }
}

// K1b: reduce split-K partials + bias -> g_att_h. Grid 512 x 256.
__global__ __launch_bounds__(256) void k1_reduce(const float* __restrict__ bias) {
    const int idx = blockIdx.x * 256 + threadIdx.x;   // < B*H
    float s = bias[idx & (H - 1)];
#pragma unroll
    for (int k = 0; k < KS; ++k) s += g_part[(size_t)k * (B * H) + idx];
    g_att_h[idx] = s;
}

// ---------------------------------------------------------------------------
// K2+K3 fused: one block per batch row.
//   scores[s] = sum_h w_alpha[h]*tanh(p[b,s,h] + att_h[b,h])   (b_alpha cancels)
//   weight = renorm(softmax(scores) * mask)
// 256 threads: 8 warps sweep s; then block softmax over smem scores.
// ---------------------------------------------------------------------------
__global__ __launch_bounds__(256) void k2_fused(const float* __restrict__ p_att,
                                                const float* __restrict__ w_alpha,
                                                const float* __restrict__ mask) {
    __shared__ __align__(16) float ah[H];
    __shared__ __align__(16) float wa[H];
    __shared__ float sc[256];
    __shared__ float red[256];

    const int b = blockIdx.x;
    const int tid = threadIdx.x;

    ah[tid]       = g_att_h[b * H + tid];
    ah[tid + 256] = g_att_h[b * H + tid + 256];
    wa[tid]       = w_alpha[tid];
    wa[tid + 256] = w_alpha[tid + 256];
    if (tid >= S) sc[tid] = -1e30f;        // pad tail for max-reduce
    __syncthreads();

    const int w = tid >> 5, l = tid & 31;

    for (int s = w; s < S; s += 8) {
        const float4* pp = (const float4*)(p_att + (size_t)(b * S + s) * H);
        float acc = 0.f;
#pragma unroll
        for (int j = 0; j < 4; ++j) {
            const int hi = j * 32 + l;               // float4 index into H/4
            float4 p4 = pp[hi];
            float4 a4 = *(const float4*)&ah[hi * 4];
            float4 w4 = *(const float4*)&wa[hi * 4];
            acc += w4.x * tanh_approx(p4.x + a4.x);
            acc += w4.y * tanh_approx(p4.y + a4.y);
            acc += w4.z * tanh_approx(p4.z + a4.z);
            acc += w4.w * tanh_approx(p4.w + a4.w);
        }
#pragma unroll
        for (int o = 16; o; o >>= 1) acc += __shfl_xor_sync(0xFFFFFFFFu, acc, o);
        if (l == 0) sc[s] = acc;
    }
    __syncthreads();

    // block softmax over sc[0..255] (tail = -1e30)
    red[tid] = sc[tid]; __syncthreads();
    for (int o = 128; o; o >>= 1) {
        if (tid < o) red[tid] = fmaxf(red[tid], red[tid + o]);
        __syncthreads();
    }
    const float mx = red[0]; __syncthreads();

    float e = (tid < S) ? __expf(sc[tid] - mx) : 0.f;
    // softmax denom and mask-renorm denom: weight = e*mask / sum(e*mask)
    // (sum(e) normalization cancels in the renorm step)
    float wgt = (tid < S) ? e * mask[b * S + tid] : 0.f;
    red[tid] = wgt; __syncthreads();
    for (int o = 128; o; o >>= 1) {
        if (tid < o) red[tid] += red[tid + o];
        __syncthreads();
    }
    const float inv = 1.f / red[0];
    if (tid < S) g_weight[b * S + tid] = wgt * inv;
}

// ---------------------------------------------------------------------------
// K4: att_res[b,d] = sum_s weight[b,s] * att_feats[b,s,d]
// Grid (B, 4); 128 threads; each thread owns 4 consecutive d (float4).
// ---------------------------------------------------------------------------
__global__ __launch_bounds__(128) void k4_wsum(const float* __restrict__ feats,
                                               float* __restrict__ out) {
    __shared__ float ws[S];
    const int b = blockIdx.x;
    const int dbase = blockIdx.y * 512 + threadIdx.x * 4;

    for (int i = threadIdx.x; i < S; i += 128) ws[i] = g_weight[b * S + i];
    __syncthreads();

    const float4* fp = (const float4*)(feats + (size_t)b * S * D + dbase);
    float4 acc = make_float4(0.f, 0.f, 0.f, 0.f);
#pragma unroll 4
    for (int s = 0; s < S; ++s) {
        float4 f = fp[(size_t)s * (D / 4)];
        const float w = ws[s];
        acc.x += w * f.x; acc.y += w * f.y;
        acc.z += w * f.z; acc.w += w * f.w;
    }
    *(float4*)(out + (size_t)b * D + dbase) = acc;
}

// ---------------------------------------------------------------------------
extern "C" void kernel_launch(void* const* d_in, const int* in_sizes, int n_in,
                              void* d_out, int out_size) {
    const float* h         = (const float*)d_in[0];   // [B,D]
    const float* att_feats = (const float*)d_in[1];   // [B,S,D]
    const float* p_att     = (const float*)d_in[2];   // [B,S,H]
    const float* mask      = (const float*)d_in[3];   // [B,S]
    const float* W         = (const float*)d_in[4];   // [H,D]
    const float* b_h2att   = (const float*)d_in[5];   // [H]
    const float* w_alpha   = (const float*)d_in[6];   // [H]
    // d_in[7] = b_alpha: cancels in softmax, unused.
    float* out = (float*)d_out;                        // [B,D]

    k1_gemm  <<<dim3(B / 64, H / 64, KS), 256>>>(h, W);
    k1_reduce<<<dim3((B * H) / 256), 256>>>(b_h2att);
    k2_fused <<<dim3(B), 256>>>(p_att, w_alpha, mask);
    k4_wsum  <<<dim3(B, 4), 128>>>(att_feats, out);
}

// round 5
// speedup vs baseline: 1.2001x; 1.0068x over previous
#include <cuda_runtime.h>

// Attention_2362232013200 — B=256, S=196, D=2048, H=512, all fp32.
// R3: k1 = 128x128 tile / 8x8 microtile split-K GEMM with FFMA2 swap-trick
//     (no per-kk operand packing); k1_reduce fused into k2; k2/k4 MLP boosts.

typedef unsigned long long ull;

constexpr int B = 256;
constexpr int S = 196;
constexpr int D = 2048;
constexpr int H = 512;
constexpr int KS = 16;          // split-K factor
constexpr int KC = D / KS;      // 128 K per split
constexpr int BK = 16;

// ---- scratch (device globals; no allocations allowed) ----
__device__ __align__(16) float g_part[KS * B * H];   // 8 MB split-K partials
__device__ __align__(16) float g_weight[B * S];      // [B,S]

__device__ __forceinline__ float tanh_approx(float x) {
    float r;
    asm("tanh.approx.f32 %0, %1;" : "=f"(r) : "f"(x));
    return r;
}
__device__ __forceinline__ ull pack2(float lo, float hi) {
    ull r; asm("mov.b64 %0, {%1, %2};" : "=l"(r) : "f"(lo), "f"(hi)); return r;
}
__device__ __forceinline__ void unpack2(ull v, float& lo, float& hi) {
    asm("mov.b64 {%0, %1}, %2;" : "=f"(lo), "=f"(hi) : "l"(v));
}
__device__ __forceinline__ ull swap2(ull v) {
    float lo, hi; unpack2(v, lo, hi); return pack2(hi, lo);
}
__device__ __forceinline__ void ffma2(ull& acc, ull a, ull b) {
    asm("fma.rn.f32x2 %0, %1, %2, %0;" : "+l"(acc) : "l"(a), "l"(b));
}

// ---------------------------------------------------------------------------
// K1: split-K SGEMM partials. part[z][b][h] = sum_{k in chunk} h[b,k]*W[h,k]
// BM=BN=128, BK=16, 256 threads, 8x8 microtile via FFMA2 pairs.
// accd[mp][np] = (c[2mp][2np],   c[2mp+1][2np+1])
// accx[mp][np] = (c[2mp+1][2np], c[2mp][2np+1])
// Grid: (256/128, 512/128, KS) = (2, 4, 16) = 128 blocks.
// ---------------------------------------------------------------------------
__global__ __launch_bounds__(256) void k1_gemm(const float* __restrict__ A,
                                               const float* __restrict__ Wm) {
    __shared__ __align__(16) float As[BK][132];   // [k][m], padded
    __shared__ __align__(16) float Bs[BK][132];   // [k][n], padded

    const int bm = blockIdx.x * 128;
    const int bn = blockIdx.y * 128;
    const int k0 = blockIdx.z * KC;

    const int tid = threadIdx.x;
    const int tx = tid & 15;          // n-group (8 wide)
    const int ty = tid >> 4;          // m-group (8 wide)

    // loader: thread covers rows r0 and r0+64, k-offset ko..ko+3
    const int r0 = tid >> 2;
    const int ko = (tid & 3) * 4;

    const float* Ap = A  + (size_t)(bm + r0) * D + k0 + ko;
    const float* Bp = Wm + (size_t)(bn + r0) * D + k0 + ko;

    ull accd[4][4] = {};
    ull accx[4][4] = {};

    for (int kt = 0; kt < KC / BK; ++kt) {
        float4 a0 = *(const float4*)(Ap + kt * BK);
        float4 a1 = *(const float4*)(Ap + kt * BK + (size_t)64 * D);
        float4 b0 = *(const float4*)(Bp + kt * BK);
        float4 b1 = *(const float4*)(Bp + kt * BK + (size_t)64 * D);
        if (kt) __syncthreads();
        As[ko + 0][r0] = a0.x; As[ko + 1][r0] = a0.y;
        As[ko + 2][r0] = a0.z; As[ko + 3][r0] = a0.w;
        As[ko + 0][r0 + 64] = a1.x; As[ko + 1][r0 + 64] = a1.y;
        As[ko + 2][r0 + 64] = a1.z; As[ko + 3][r0 + 64] = a1.w;
        Bs[ko + 0][r0] = b0.x; Bs[ko + 1][r0] = b0.y;
        Bs[ko + 2][r0] = b0.z; Bs[ko + 3][r0] = b0.w;
        Bs[ko + 0][r0 + 64] = b1.x; Bs[ko + 1][r0 + 64] = b1.y;
        Bs[ko + 2][r0 + 64] = b1.z; Bs[ko + 3][r0 + 64] = b1.w;
        __syncthreads();
#pragma unroll
        for (int kk = 0; kk < BK; ++kk) {
            const ull* ap = (const ull*)&As[kk][ty * 8];
            const ull* bp = (const ull*)&Bs[kk][tx * 8];
            ull pa[4], pb[4], sa[4];
#pragma unroll
            for (int i = 0; i < 4; ++i) { pa[i] = ap[i]; pb[i] = bp[i]; }
#pragma unroll
            for (int i = 0; i < 4; ++i) sa[i] = swap2(pa[i]);
#pragma unroll
            for (int np = 0; np < 4; ++np)
#pragma unroll
                for (int mp = 0; mp < 4; ++mp) {
                    ffma2(accd[mp][np], pa[mp], pb[np]);
                    ffma2(accx[mp][np], sa[mp], pb[np]);
                }
        }
    }

    float* po = g_part + (size_t)blockIdx.z * (B * H) +
                (size_t)(bm + ty * 8) * H + bn + tx * 8;
#pragma unroll
    for (int mp = 0; mp < 4; ++mp) {
        float e0[8], e1[8];
#pragma unroll
        for (int np = 0; np < 4; ++np) {
            float dlo, dhi, xlo, xhi;
            unpack2(accd[mp][np], dlo, dhi);
            unpack2(accx[mp][np], xlo, xhi);
            e0[2 * np] = dlo; e0[2 * np + 1] = xhi;   // row 2mp
            e1[2 * np] = xlo; e1[2 * np + 1] = dhi;   // row 2mp+1
        }
        float* r0p = po + (size_t)(2 * mp) * H;
        float* r1p = po + (size_t)(2 * mp + 1) * H;
        *(float4*)(r0p)     = make_float4(e0[0], e0[1], e0[2], e0[3]);
        *(float4*)(r0p + 4) = make_float4(e0[4], e0[5], e0[6], e0[7]);
        *(float4*)(r1p)     = make_float4(e1[0], e1[1], e1[2], e1[3]);
        *(float4*)(r1p + 4) = make_float4(e1[4], e1[5], e1[6], e1[7]);
    }
}

// ---------------------------------------------------------------------------
// K2: fused split-K reduce + scores + softmax + mask renorm. One block per b.
//   ah[h] = bias[h] + sum_z part[z][b][h]
//   scores[s] = sum_h w_alpha[h]*tanh(p[b,s,h] + ah[h])   (b_alpha cancels)
//   weight = (softmax(scores)*mask) / sum(...)
// 256 threads; each warp handles rows s and s+98 together (2x MLP).
// ---------------------------------------------------------------------------
__global__ __launch_bounds__(256) void k2_fused(const float* __restrict__ p_att,
                                                const float* __restrict__ w_alpha,
                                                const float* __restrict__ bias,
                                                const float* __restrict__ mask) {
    __shared__ __align__(16) float ah[H];
    __shared__ __align__(16) float wa[H];
    __shared__ float sc[256];
    __shared__ float red[256];

    const int b = blockIdx.x;
    const int tid = threadIdx.x;

    for (int i = tid; i < H; i += 256) {
        float s = bias[i];
#pragma unroll
        for (int z = 0; z < KS; ++z) s += g_part[(size_t)z * (B * H) + b * H + i];
        ah[i] = s;
        wa[i] = w_alpha[i];
    }
    if (tid >= S) sc[tid] = -1e30f;        // pad tail for max-reduce
    __syncthreads();

    const int w = tid >> 5, l = tid & 31;

    for (int s = w; s < 98; s += 8) {       // pairs (s, s+98) cover 0..195
        const float4* pp0 = (const float4*)(p_att + (size_t)(b * S + s) * H);
        const float4* pp1 = (const float4*)(p_att + (size_t)(b * S + s + 98) * H);
        float acc0 = 0.f, acc1 = 0.f;
#pragma unroll
        for (int j = 0; j < 4; ++j) {
            const int hi = j * 32 + l;               // float4 index into H/4
            float4 p0 = pp0[hi];
            float4 p1 = pp1[hi];
            float4 a4 = *(const float4*)&ah[hi * 4];
            float4 w4 = *(const float4*)&wa[hi * 4];
            acc0 += w4.x * tanh_approx(p0.x + a4.x);
            acc0 += w4.y * tanh_approx(p0.y + a4.y);
            acc0 += w4.z * tanh_approx(p0.z + a4.z);
            acc0 += w4.w * tanh_approx(p0.w + a4.w);
            acc1 += w4.x * tanh_approx(p1.x + a4.x);
            acc1 += w4.y * tanh_approx(p1.y + a4.y);
            acc1 += w4.z * tanh_approx(p1.z + a4.z);
            acc1 += w4.w * tanh_approx(p1.w + a4.w);
        }
#pragma unroll
        for (int o = 16; o; o >>= 1) {
            acc0 += __shfl_xor_sync(0xFFFFFFFFu, acc0, o);
            acc1 += __shfl_xor_sync(0xFFFFFFFFu, acc1, o);
        }
        if (l == 0) { sc[s] = acc0; sc[s + 98] = acc1; }
    }
    __syncthreads();

    // block softmax over sc[0..255] (tail = -1e30)
    red[tid] = sc[tid]; __syncthreads();
    for (int o = 128; o; o >>= 1) {
        if (tid < o) red[tid] = fmaxf(red[tid], red[tid + o]);
        __syncthreads();
    }
    const float mx = red[0]; __syncthreads();

    // weight = e*mask / sum(e*mask): softmax denom cancels with renorm denom
    float wgt = (tid < S) ? __expf(sc[tid] - mx) * mask[b * S + tid] : 0.f;
    red[tid] = wgt; __syncthreads();
    for (int o = 128; o; o >>= 1) {
        if (tid < o) red[tid] += red[tid + o];
        __syncthreads();
    }
    const float inv = 1.f / red[0];
    if (tid < S) g_weight[b * S + tid] = wgt * inv;
}

// ---------------------------------------------------------------------------
// K4: att_res[b,d] = sum_s weight[b,s] * att_feats[b,s,d]
// Grid (B, 2); 256 threads; thread owns one float4; s unrolled x2, dual acc.
// ---------------------------------------------------------------------------
__global__ __launch_bounds__(256, 1) void k4_wsum(const float* __restrict__ feats,
                                                  float* __restrict__ out) {
    __shared__ float ws[S];
    const int b = blockIdx.x;
    const int dbase = blockIdx.y * 1024 + threadIdx.x * 4;

    if (threadIdx.x < S) ws[threadIdx.x] = g_weight[b * S + threadIdx.x];
    __syncthreads();

    const float4* fp = (const float4*)(feats + (size_t)b * S * D + dbase);
    float4 acc0 = make_float4(0.f, 0.f, 0.f, 0.f);
    float4 acc1 = make_float4(0.f, 0.f, 0.f, 0.f);
#pragma unroll 4
    for (int s = 0; s < S; s += 2) {
        float4 f0 = fp[(size_t)s * (D / 4)];
        float4 f1 = fp[(size_t)(s + 1) * (D / 4)];
        const float w0 = ws[s];
        const float w1 = ws[s + 1];
        acc0.x += w0 * f0.x; acc0.y += w0 * f0.y;
        acc0.z += w0 * f0.z; acc0.w += w0 * f0.w;
        acc1.x += w1 * f1.x; acc1.y += w1 * f1.y;
        acc1.z += w1 * f1.z; acc1.w += w1 * f1.w;
    }
    *(float4*)(out + (size_t)b * D + dbase) =
        make_float4(acc0.x + acc1.x, acc0.y + acc1.y,
                    acc0.z + acc1.z, acc0.w + acc1.w);
}

// ---------------------------------------------------------------------------
extern "C" void kernel_launch(void* const* d_in, const int* in_sizes, int n_in,
                              void* d_out, int out_size) {
    const float* h         = (const float*)d_in[0];   // [B,D]
    const float* att_feats = (const float*)d_in[1];   // [B,S,D]
    const float* p_att     = (const float*)d_in[2];   // [B,S,H]
    const float* mask      = (const float*)d_in[3];   // [B,S]
    const float* W         = (const float*)d_in[4];   // [H,D]
    const float* b_h2att   = (const float*)d_in[5];   // [H]
    const float* w_alpha   = (const float*)d_in[6];   // [H]
    // d_in[7] = b_alpha: cancels in softmax, unused.
    float* out = (float*)d_out;                        // [B,D]

    k1_gemm <<<dim3(2, 4, KS), 256>>>(h, W);
    k2_fused<<<dim3(B), 256>>>(p_att, w_alpha, b_h2att, mask);
    k4_wsum <<<dim3(B, 2), 256>>>(att_feats, out);
}